// round 10
// baseline (speedup 1.0000x reference)
#include <cuda_runtime.h>
#include <cstdint>

// MatchNet: per-row MLP(6->20->20->20->8, tanh) + 150-iter PDHG LP.
// R10: pair-split PDHG — 2 threads per row (even lanes: x0-3/y0-2, odd
// lanes: x4-7/y3-5). 2048 warps (2x occupancy) to pack the fma pipe across
// rsqrt windows. Cross-half traffic: 8 SHFL.XOR(1)/iter (MIO); half-dependent
// operands via FSEL (alu). Arithmetic bit-identical to R9 per lane.

#define NTHREADS 64
#define PDHG_ITERS 150

#define TAU  0.18898223650461357f   /* 1/sqrt(28) */
#define SGM  0.18898223650461357f   /* sigma = tau */
#define TCC  1.8898223650461357f    /* tau * control_strength(10) */

typedef unsigned long long u64;

__device__ __forceinline__ u64 pk(float a, float b) {
    u64 r; asm("mov.b64 %0, {%1, %2};" : "=l"(r) : "f"(a), "f"(b)); return r;
}
__device__ __forceinline__ void upk(float& a, float& b, u64 p) {
    asm("mov.b64 {%0, %1}, %2;" : "=f"(a), "=f"(b) : "l"(p));
}
__device__ __forceinline__ u64 fma2(u64 a, u64 b, u64 c) {
    u64 d; asm("fma.rn.f32x2 %0, %1, %2, %3;" : "=l"(d) : "l"(a), "l"(b), "l"(c)); return d;
}
__device__ __forceinline__ float fast_rsqrt(float v) {
    float r; asm("rsqrt.approx.f32 %0, %1;" : "=f"(r) : "f"(v)); return r;
}
__device__ __forceinline__ float fast_tanh(float x) {
    float e = __expf(2.0f * x);
    return 1.0f - __fdividef(2.0f, e + 1.0f);
}
__device__ __forceinline__ float xshfl(float v) {           // partner exchange
    return __shfl_xor_sync(0xffffffffu, v, 1);
}
// branch-free select (FSEL): c true -> a, else b
__device__ __forceinline__ float fsel(bool c, float a, float b) {
    return c ? a : b;
}

__global__ __launch_bounds__(NTHREADS)
void matchnet_kernel(
    const float* __restrict__ X,
    const float* __restrict__ W1, const float* __restrict__ b1,
    const float* __restrict__ W2, const float* __restrict__ b2,
    const float* __restrict__ W3, const float* __restrict__ b3,
    const float* __restrict__ W4, const float* __restrict__ b4,
    float* __restrict__ out, int B)
{
    __shared__ __align__(16) float sW1[120], sW2[400], sW3[400], sW4[160];
    __shared__ __align__(16) float sb1[20], sb2[20], sb3[20], sb4[8];

    const int t = threadIdx.x;
    for (int i = t; i < 120; i += NTHREADS) sW1[i] = W1[i];
    for (int i = t; i < 400; i += NTHREADS) sW2[i] = W2[i];
    for (int i = t; i < 400; i += NTHREADS) sW3[i] = W3[i];
    for (int i = t; i < 160; i += NTHREADS) sW4[i] = W4[i];
    if (t < 20) { sb1[t] = b1[t]; sb2[t] = b2[t]; sb3[t] = b3[t]; }
    if (t < 8)  { sb4[t] = b4[t]; }
    __syncthreads();

    const int gt  = blockIdx.x * NTHREADS + t;
    const int row = gt >> 1;
    const bool odd = (gt & 1) != 0;
    if (row >= B) return;

    // ---- input row (both pair threads load the same row; L1 broadcast) ----
    float Z0, Z1, Z2, Z3, Z4, Z5;
    {
        const float2* p = (const float2*)(X + row * 6);
        float2 a0 = p[0], a1 = p[1], a2 = p[2];
        Z0 = a0.x; Z1 = a0.y; Z2 = a1.x;
        Z3 = a1.y; Z4 = a2.x; Z5 = a2.y;
    }

    // ---- MLP (redundant per pair; f32x2-packed, validated R6-R9) ----
    float h[20], h2[20];
    {
        float Zv[6] = {Z0, Z1, Z2, Z3, Z4, Z5};
        u64 a[10];
#pragma unroll
        for (int jp = 0; jp < 10; jp++) a[jp] = *(const u64*)&sb1[2 * jp];
#pragma unroll
        for (int k = 0; k < 6; k++) {
            u64 zz = pk(Zv[k], Zv[k]);
#pragma unroll
            for (int jp = 0; jp < 10; jp++)
                a[jp] = fma2(zz, *(const u64*)&sW1[k * 20 + 2 * jp], a[jp]);
        }
#pragma unroll
        for (int jp = 0; jp < 10; jp++) {
            float s0, s1; upk(s0, s1, a[jp]);
            h[2 * jp] = fast_tanh(s0); h[2 * jp + 1] = fast_tanh(s1);
        }
    }
    {
        u64 a[10];
#pragma unroll
        for (int jp = 0; jp < 10; jp++) a[jp] = *(const u64*)&sb2[2 * jp];
#pragma unroll
        for (int k = 0; k < 20; k++) {
            u64 hh = pk(h[k], h[k]);
#pragma unroll
            for (int jp = 0; jp < 10; jp++)
                a[jp] = fma2(hh, *(const u64*)&sW2[k * 20 + 2 * jp], a[jp]);
        }
#pragma unroll
        for (int jp = 0; jp < 10; jp++) {
            float s0, s1; upk(s0, s1, a[jp]);
            h2[2 * jp] = fast_tanh(s0); h2[2 * jp + 1] = fast_tanh(s1);
        }
    }
    {
        u64 a[10];
#pragma unroll
        for (int jp = 0; jp < 10; jp++) a[jp] = *(const u64*)&sb3[2 * jp];
#pragma unroll
        for (int k = 0; k < 20; k++) {
            u64 hh = pk(h2[k], h2[k]);
#pragma unroll
            for (int jp = 0; jp < 10; jp++)
                a[jp] = fma2(hh, *(const u64*)&sW3[k * 20 + 2 * jp], a[jp]);
        }
#pragma unroll
        for (int jp = 0; jp < 10; jp++) {
            float s0, s1; upk(s0, s1, a[jp]);
            h[2 * jp] = fast_tanh(s0); h[2 * jp + 1] = fast_tanh(s1);
        }
    }
    float z[8];
    {
        u64 a[4];
#pragma unroll
        for (int jp = 0; jp < 4; jp++) a[jp] = *(const u64*)&sb4[2 * jp];
#pragma unroll
        for (int k = 0; k < 20; k++) {
            u64 hh = pk(h[k], h[k]);
#pragma unroll
            for (int jp = 0; jp < 4; jp++)
                a[jp] = fma2(hh, *(const u64*)&sW4[k * 8 + 2 * jp], a[jp]);
        }
#pragma unroll
        for (int jp = 0; jp < 4; jp++) upk(z[2 * jp], z[2 * jp + 1], a[jp]);
    }

    // ---- own-lane z (even: 0-3, odd: 4-7); hoisted Z selects ----
    float zo0 = fsel(odd, z[4], z[0]);
    float zo1 = fsel(odd, z[5], z[1]);
    float zo2 = fsel(odd, z[6], z[2]);
    float zo3 = fsel(odd, z[7], z[3]);
    const float ZA = fsel(odd, Z3, Z0);
    const float ZB = fsel(odd, Z4, Z1);
    const float ZC = fsel(odd, Z5, Z2);

    // ---- PDHG state (own 4 lanes + own 3 duals) ----
    // x0 = max(zo,0); sdn = x0 - zo; xb = x0; zm = zo - sdn; y = 0; w = 1.
    float x00 = fmaxf(zo0, 0.0f), x01 = fmaxf(zo1, 0.0f);
    float x02 = fmaxf(zo2, 0.0f), x03 = fmaxf(zo3, 0.0f);
    float sdn0 = x00 - zo0, sdn1 = x01 - zo1, sdn2 = x02 - zo2, sdn3 = x03 - zo3;
    float xb0 = x00, xb1 = x01, xb2 = x02, xb3 = x03;
    float zm0 = zo0 - sdn0, zm1 = zo1 - sdn1, zm2 = zo2 - sdn2, zm3 = zo3 - sdn3;
    float ya = 0.f, yb = 0.f, yc = 0.f;            // even: y0,y1,y2 ; odd: y3,y4,y5
    float w0 = 1.f, w1 = 1.f, w2 = 1.f, w3 = 1.f;  // YIp of own x-lanes

#pragma unroll 2
    for (int it = 0; it < PDHG_ITERS; it++) {
        // ---- exchange xb with partner (b = partner's 4 lanes) ----
        float bb0 = xshfl(xb0), bb1 = xshfl(xb1), bb2 = xshfl(xb2), bb3 = xshfl(xb3);

        // ---- s = S*xb - Z for own 3 rows (bit-identical to R9 association) ----
        // pair sums with half-selected operands
        float P1 = fsel(odd, bb2, xb0) + fsel(odd, bb3, xb2); // e: xb0+xb2 | o: xb2+xb3
        float P2 = bb1 + fsel(odd, bb2, bb3);                 // e: xb5+xb7 | o: xb1+xb2
        float P3 = fsel(odd, xb0, xb1) + xb3;                 // e: xb1+xb3 | o: xb4+xb7
        float P4 = fsel(odd, bb0, xb0) + fsel(odd, xb0, xb1); // e: xb0+xb1 | o: xb0+xb4
        float w1s = fsel(odd, xb1, bb0);                      // e: xb4 | o: xb5
        float w2s = fsel(odd, xb2, bb2);                      // xb6 both halves
        float m1  = fsel(odd, w1s, P2);
        float sA  = P1 + (m1 - ZA);                           // e: s0 | o: s3
        float n1  = fsel(odd, P2, P3);
        float n2  = fsel(odd, P3, w1s);
        float sB  = n1 + (n2 - ZB);                           // e: s1 | o: s4
        float sC  = P4 + (w2s - ZC);                          // e: s2 | o: s5

        // ---- dual updates (own) ----
        ya = fmaxf(0.0f, fmaf(SGM, sA, ya));
        yb = fmaxf(0.0f, fmaf(SGM, sB, yb));
        yc = fmaxf(0.0f, fmaf(SGM, sC, yc));
        w0 = fmaxf(1.0f, fmaf(-SGM, xb0, w0));
        w1 = fmaxf(1.0f, fmaf(-SGM, xb1, w1));
        w2 = fmaxf(1.0f, fmaf(-SGM, xb2, w2));
        w3 = fmaxf(1.0f, fmaf(-SGM, xb3, w3));

        // ---- exchange y; build full Y0..Y5 ----
        float oya = xshfl(ya), oyb = xshfl(yb), oyc = xshfl(yc);
        float Y0 = fsel(odd, oya, ya);
        float Y1 = fsel(odd, oyb, yb);
        float Y2 = fsel(odd, oyc, yc);
        float Y3 = fsel(odd, ya, oya);
        float Y4 = fsel(odd, yb, oyb);
        float Y5 = fsel(odd, yc, oyc);

        // ---- gy = S^T y - YIp for own 4 columns (R9 association) ----
        float q25 = Y2 + Y5, q04 = Y0 + Y4, q14 = Y1 + Y4;
        float gy0 = (fsel(odd, q14, Y0) + fsel(odd, Y5, q25)) - w0; // e: gy0 | o: gy4
        float gy1 = (fsel(odd, Y0, q14) + fsel(odd, Y3, Y2)) - w1;  // e: gy1 | o: gy5
        float gy2 = (fsel(odd, q25, q04) + fsel(odd, 0.0f, Y3)) - w2; // e: gy2 | o: gy6
        float gy3 = (fsel(odd, q04, Y1) + fsel(odd, 0.0f, Y3)) - w3;  // e: gy3 | o: gy7

        // ---- d = sdn - tau*gy (own) ----
        float d0 = fmaf(-TAU, gy0, sdn0);
        float d1 = fmaf(-TAU, gy1, sdn1);
        float d2 = fmaf(-TAU, gy2, sdn2);
        float d3 = fmaf(-TAU, gy3, sdn3);

        // ---- ||d||^2: own half-tree + butterfly (commutative-exact) ----
        float pp = fmaf(d0, d0, d1 * d1);
        float qq = fmaf(d2, d2, d3 * d3);
        float half_nn = pp + qq;
        float nn = half_nn + xshfl(half_nn);
        float rr = fast_rsqrt(nn);
        float scale = fmaxf(0.0f, fmaf(-TCC, rr, 1.0f));

        // ---- primal (own) ----
        float ns0 = scale * d0, ns1 = scale * d1, ns2 = scale * d2, ns3 = scale * d3;
        xb0 = fmaf(2.0f, ns0, zm0); zm0 = zo0 - ns0; sdn0 = ns0;
        xb1 = fmaf(2.0f, ns1, zm1); zm1 = zo1 - ns1; sdn1 = ns1;
        xb2 = fmaf(2.0f, ns2, zm2); zm2 = zo2 - ns2; sdn2 = ns2;
        xb3 = fmaf(2.0f, ns3, zm3); zm3 = zo3 - ns3; sdn3 = ns3;
    }

    // ---- x = zo + sdn ; each thread stores its 4 lanes (coalesced 16B) ----
    float4* p = (float4*)(out + row * 8 + (odd ? 4 : 0));
    *p = make_float4(zo0 + sdn0, zo1 + sdn1, zo2 + sdn2, zo3 + sdn3);
}

extern "C" void kernel_launch(void* const* d_in, const int* in_sizes, int n_in,
                              void* d_out, int out_size) {
    const float* X  = (const float*)d_in[0];
    const float* W1 = (const float*)d_in[1];
    const float* b1 = (const float*)d_in[2];
    const float* W2 = (const float*)d_in[3];
    const float* b2 = (const float*)d_in[4];
    const float* W3 = (const float*)d_in[5];
    const float* b3 = (const float*)d_in[6];
    const float* W4 = (const float*)d_in[7];
    const float* b4 = (const float*)d_in[8];

    const int B = in_sizes[0] / 6;
    const long long threads = 2LL * B;
    const int grid = (int)((threads + NTHREADS - 1) / NTHREADS);
    matchnet_kernel<<<grid, NTHREADS>>>(X, W1, b1, W2, b2, W3, b3, W4, b4,
                                        (float*)d_out, B);
}

// round 11
// speedup vs baseline: 1.4202x; 1.4202x over previous
#include <cuda_runtime.h>

// MatchNet: per-row MLP(6->20->20->20->8, tanh) + 150-iter PDHG LP.
// R11 = R9 (best, 33.2us) with two fma-pipe op cuts (95 -> 89 ops/iter):
//  - shared-pair S*xb gather: A=xb2+xb5 (rows 0,3), B=xb1+xb4 (rows 1,4),
//    C=xb0+xb6 (rows 2,5): 17 adds incl Z folds (was 20).
//  - serial-chain ||d||^2: 1 mul + 7 fma (was 11); chain slack is ample
//    since the kernel is fma-pipe-occupancy bound (380 cyc/iter/SMSP-pair),
//    not chain bound (~130 cyc).

#define NTHREADS 32
#define PDHG_ITERS 150

#define TAU  0.18898223650461357f   /* 1/sqrt(28) */
#define SGM  0.18898223650461357f   /* sigma = tau */
#define TCC  1.8898223650461357f    /* tau * control_strength(10) */

typedef unsigned long long u64;

__device__ __forceinline__ u64 pk(float a, float b) {
    u64 r; asm("mov.b64 %0, {%1, %2};" : "=l"(r) : "f"(a), "f"(b)); return r;
}
__device__ __forceinline__ void upk(float& a, float& b, u64 p) {
    asm("mov.b64 {%0, %1}, %2;" : "=f"(a), "=f"(b) : "l"(p));
}
__device__ __forceinline__ u64 fma2(u64 a, u64 b, u64 c) {
    u64 d; asm("fma.rn.f32x2 %0, %1, %2, %3;" : "=l"(d) : "l"(a), "l"(b), "l"(c)); return d;
}
__device__ __forceinline__ float fast_rsqrt(float v) {
    float r; asm("rsqrt.approx.f32 %0, %1;" : "=f"(r) : "f"(v)); return r;
}
__device__ __forceinline__ float fast_tanh(float x) {
    float e = __expf(2.0f * x);
    return 1.0f - __fdividef(2.0f, e + 1.0f);
}

__global__ __launch_bounds__(NTHREADS)
void matchnet_kernel(
    const float* __restrict__ X,
    const float* __restrict__ W1, const float* __restrict__ b1,
    const float* __restrict__ W2, const float* __restrict__ b2,
    const float* __restrict__ W3, const float* __restrict__ b3,
    const float* __restrict__ W4, const float* __restrict__ b4,
    float* __restrict__ out, int B)
{
    __shared__ __align__(16) float sW1[120], sW2[400], sW3[400], sW4[160];
    __shared__ __align__(16) float sb1[20], sb2[20], sb3[20], sb4[8];

    const int t = threadIdx.x;
    for (int i = t; i < 120; i += NTHREADS) sW1[i] = W1[i];
    for (int i = t; i < 400; i += NTHREADS) sW2[i] = W2[i];
    for (int i = t; i < 400; i += NTHREADS) sW3[i] = W3[i];
    for (int i = t; i < 160; i += NTHREADS) sW4[i] = W4[i];
    if (t < 20) { sb1[t] = b1[t]; sb2[t] = b2[t]; sb3[t] = b3[t]; }
    if (t < 8)  { sb4[t] = b4[t]; }
    __syncthreads();

    const int row = blockIdx.x * NTHREADS + t;
    if (row >= B) return;

    // ---- input row (RHS b of the LP) ----
    float Z0, Z1, Z2, Z3, Z4, Z5;
    {
        const float2* p = (const float2*)(X + row * 6);
        float2 a0 = p[0], a1 = p[1], a2 = p[2];
        Z0 = a0.x; Z1 = a0.y; Z2 = a1.x;
        Z3 = a1.y; Z4 = a2.x; Z5 = a2.y;
    }

    // ---- MLP, f32x2-packed (validated R6-R9) ----
    float h[20], h2[20];
    {
        float Zv[6] = {Z0, Z1, Z2, Z3, Z4, Z5};
        u64 a[10];
#pragma unroll
        for (int jp = 0; jp < 10; jp++) a[jp] = *(const u64*)&sb1[2 * jp];
#pragma unroll
        for (int k = 0; k < 6; k++) {
            u64 zz = pk(Zv[k], Zv[k]);
#pragma unroll
            for (int jp = 0; jp < 10; jp++)
                a[jp] = fma2(zz, *(const u64*)&sW1[k * 20 + 2 * jp], a[jp]);
        }
#pragma unroll
        for (int jp = 0; jp < 10; jp++) {
            float s0, s1; upk(s0, s1, a[jp]);
            h[2 * jp] = fast_tanh(s0); h[2 * jp + 1] = fast_tanh(s1);
        }
    }
    {
        u64 a[10];
#pragma unroll
        for (int jp = 0; jp < 10; jp++) a[jp] = *(const u64*)&sb2[2 * jp];
#pragma unroll
        for (int k = 0; k < 20; k++) {
            u64 hh = pk(h[k], h[k]);
#pragma unroll
            for (int jp = 0; jp < 10; jp++)
                a[jp] = fma2(hh, *(const u64*)&sW2[k * 20 + 2 * jp], a[jp]);
        }
#pragma unroll
        for (int jp = 0; jp < 10; jp++) {
            float s0, s1; upk(s0, s1, a[jp]);
            h2[2 * jp] = fast_tanh(s0); h2[2 * jp + 1] = fast_tanh(s1);
        }
    }
    {
        u64 a[10];
#pragma unroll
        for (int jp = 0; jp < 10; jp++) a[jp] = *(const u64*)&sb3[2 * jp];
#pragma unroll
        for (int k = 0; k < 20; k++) {
            u64 hh = pk(h2[k], h2[k]);
#pragma unroll
            for (int jp = 0; jp < 10; jp++)
                a[jp] = fma2(hh, *(const u64*)&sW3[k * 20 + 2 * jp], a[jp]);
        }
#pragma unroll
        for (int jp = 0; jp < 10; jp++) {
            float s0, s1; upk(s0, s1, a[jp]);
            h[2 * jp] = fast_tanh(s0); h[2 * jp + 1] = fast_tanh(s1);
        }
    }
    float z[8];
    {
        u64 a[4];
#pragma unroll
        for (int jp = 0; jp < 4; jp++) a[jp] = *(const u64*)&sb4[2 * jp];
#pragma unroll
        for (int k = 0; k < 20; k++) {
            u64 hh = pk(h[k], h[k]);
#pragma unroll
            for (int jp = 0; jp < 4; jp++)
                a[jp] = fma2(hh, *(const u64*)&sW4[k * 8 + 2 * jp], a[jp]);
        }
#pragma unroll
        for (int jp = 0; jp < 4; jp++) upk(z[2 * jp], z[2 * jp + 1], a[jp]);
    }

    // ---- PDHG state init (no prologue; loop iter 1 == reference step 1) ----
    float sdn0, sdn1, sdn2, sdn3, sdn4, sdn5, sdn6, sdn7;
    float xb0, xb1, xb2, xb3, xb4, xb5, xb6, xb7;
    float zm0, zm1, zm2, zm3, zm4, zm5, zm6, zm7;
    {
        float x00 = fmaxf(z[0], 0.0f), x01 = fmaxf(z[1], 0.0f);
        float x02 = fmaxf(z[2], 0.0f), x03 = fmaxf(z[3], 0.0f);
        float x04 = fmaxf(z[4], 0.0f), x05 = fmaxf(z[5], 0.0f);
        float x06 = fmaxf(z[6], 0.0f), x07 = fmaxf(z[7], 0.0f);
        sdn0 = x00 - z[0]; sdn1 = x01 - z[1]; sdn2 = x02 - z[2]; sdn3 = x03 - z[3];
        sdn4 = x04 - z[4]; sdn5 = x05 - z[5]; sdn6 = x06 - z[6]; sdn7 = x07 - z[7];
        xb0 = x00; xb1 = x01; xb2 = x02; xb3 = x03;
        xb4 = x04; xb5 = x05; xb6 = x06; xb7 = x07;
        zm0 = z[0] - sdn0; zm1 = z[1] - sdn1; zm2 = z[2] - sdn2; zm3 = z[3] - sdn3;
        zm4 = z[4] - sdn4; zm5 = z[5] - sdn5; zm6 = z[6] - sdn6; zm7 = z[7] - sdn7;
    }
    float y0 = 0.f, y1 = 0.f, y2 = 0.f, y3 = 0.f, y4 = 0.f, y5 = 0.f;
    float w0 = 1.f, w1 = 1.f, w2 = 1.f, w3 = 1.f,   // YIp = yI + 1
          w4 = 1.f, w5 = 1.f, w6 = 1.f, w7 = 1.f;

#pragma unroll 2
    for (int it = 0; it < PDHG_ITERS; it++) {
        // ---- s = S*xb - Z via shared pairs (17 adds) ----
        // A = xb2+xb5 (rows 0,3); B = xb1+xb4 (rows 1,4); C = xb0+xb6 (rows 2,5)
        float A = xb2 + xb5;
        float Bp = xb1 + xb4;
        float C = xb0 + xb6;
        float s0 = ((xb0 + xb7) - Z0) + A;     // {0,2,5,7}
        float s1 = Bp + (xb3 - Z1);            // {1,3,4}
        float s2 = C + (xb1 - Z2);             // {0,1,6}
        float s3 = A + (xb3 - Z3);             // {2,3,5}
        float s4 = (Bp - Z4) + (xb2 + xb7);    // {1,2,4,7}
        float s5 = C + (xb4 - Z5);             // {0,4,6}

        // ---- dual updates ----
        y0 = fmaxf(0.0f, fmaf(SGM, s0, y0));
        y1 = fmaxf(0.0f, fmaf(SGM, s1, y1));
        y2 = fmaxf(0.0f, fmaf(SGM, s2, y2));
        y3 = fmaxf(0.0f, fmaf(SGM, s3, y3));
        y4 = fmaxf(0.0f, fmaf(SGM, s4, y4));
        y5 = fmaxf(0.0f, fmaf(SGM, s5, y5));

        w0 = fmaxf(1.0f, fmaf(-SGM, xb0, w0));
        w1 = fmaxf(1.0f, fmaf(-SGM, xb1, w1));
        w2 = fmaxf(1.0f, fmaf(-SGM, xb2, w2));
        w3 = fmaxf(1.0f, fmaf(-SGM, xb3, w3));
        w4 = fmaxf(1.0f, fmaf(-SGM, xb4, w4));
        w5 = fmaxf(1.0f, fmaf(-SGM, xb5, w5));
        w6 = fmaxf(1.0f, fmaf(-SGM, xb6, w6));
        w7 = fmaxf(1.0f, fmaf(-SGM, xb7, w7));

        // ---- gy = S^T y - YIp (9 adds + 8 subs, q-reuse) ----
        float q25 = y2 + y5, q04 = y0 + y4, q14 = y1 + y4;
        float gy0 = (y0 + q25) - w0;
        float gy1 = (q14 + y2) - w1;
        float gy2 = (q04 + y3) - w2;
        float gy3 = (y1 + y3) - w3;
        float gy4 = (q14 + y5) - w4;
        float gy5 = (y0 + y3) - w5;
        float gy6 = q25 - w6;
        float gy7 = q04 - w7;

        // ---- d = sdn - tau*gy ----
        float d0 = fmaf(-TAU, gy0, sdn0);
        float d1 = fmaf(-TAU, gy1, sdn1);
        float d2 = fmaf(-TAU, gy2, sdn2);
        float d3 = fmaf(-TAU, gy3, sdn3);
        float d4 = fmaf(-TAU, gy4, sdn4);
        float d5 = fmaf(-TAU, gy5, sdn5);
        float d6 = fmaf(-TAU, gy6, sdn6);
        float d7 = fmaf(-TAU, gy7, sdn7);

        // ---- ||d||^2 serial chain (8 ops); rsqrt; scale ----
        float nn = d0 * d0;
        nn = fmaf(d1, d1, nn);
        nn = fmaf(d2, d2, nn);
        nn = fmaf(d3, d3, nn);
        nn = fmaf(d4, d4, nn);
        nn = fmaf(d5, d5, nn);
        nn = fmaf(d6, d6, nn);
        nn = fmaf(d7, d7, nn);
        float rr = fast_rsqrt(nn);   // nn=0 -> rr=inf -> scale=0 (exact)
        float scale = fmaxf(0.0f, fmaf(-TCC, rr, 1.0f));

        // ---- primal: ns = scale*d; xb = 2*ns + zm; zm = z - ns ----
        float ns0 = scale * d0, ns1 = scale * d1, ns2 = scale * d2, ns3 = scale * d3;
        float ns4 = scale * d4, ns5 = scale * d5, ns6 = scale * d6, ns7 = scale * d7;

        xb0 = fmaf(2.0f, ns0, zm0); zm0 = z[0] - ns0; sdn0 = ns0;
        xb1 = fmaf(2.0f, ns1, zm1); zm1 = z[1] - ns1; sdn1 = ns1;
        xb2 = fmaf(2.0f, ns2, zm2); zm2 = z[2] - ns2; sdn2 = ns2;
        xb3 = fmaf(2.0f, ns3, zm3); zm3 = z[3] - ns3; sdn3 = ns3;
        xb4 = fmaf(2.0f, ns4, zm4); zm4 = z[4] - ns4; sdn4 = ns4;
        xb5 = fmaf(2.0f, ns5, zm5); zm5 = z[5] - ns5; sdn5 = ns5;
        xb6 = fmaf(2.0f, ns6, zm6); zm6 = z[6] - ns6; sdn6 = ns6;
        xb7 = fmaf(2.0f, ns7, zm7); zm7 = z[7] - ns7; sdn7 = ns7;
    }

    // ---- x = z + sdn ----
    float4* p = (float4*)(out + row * 8);
    p[0] = make_float4(z[0] + sdn0, z[1] + sdn1, z[2] + sdn2, z[3] + sdn3);
    p[1] = make_float4(z[4] + sdn4, z[5] + sdn5, z[6] + sdn6, z[7] + sdn7);
}

extern "C" void kernel_launch(void* const* d_in, const int* in_sizes, int n_in,
                              void* d_out, int out_size) {
    const float* X  = (const float*)d_in[0];
    const float* W1 = (const float*)d_in[1];
    const float* b1 = (const float*)d_in[2];
    const float* W2 = (const float*)d_in[3];
    const float* b2 = (const float*)d_in[4];
    const float* W3 = (const float*)d_in[5];
    const float* b3 = (const float*)d_in[6];
    const float* W4 = (const float*)d_in[7];
    const float* b4 = (const float*)d_in[8];

    const int B = in_sizes[0] / 6;
    const int grid = (B + NTHREADS - 1) / NTHREADS;
    matchnet_kernel<<<grid, NTHREADS>>>(X, W1, b1, W2, b2, W3, b3, W4, b4,
                                        (float*)d_out, B);
}